// round 1
// baseline (speedup 1.0000x reference)
#include <cuda_runtime.h>
#include <cuda_bf16.h>
#include <cstdint>

// ---------------------------------------------------------------------------
// BigramLM forward, GB300 sm_103a.
//
// Stage 1 (build_qkv):  QT/KT/VT[t][v][f] tables, f = h*8+d  (520 x 32 each)
// Stage 2 (build_qk):   QK[pair(t,s)][tok_t][tok_s][h] = q·k * 32^-0.5 (2.43MB, L2)
// Stage 3 (main):       one batch per THREAD. Attention via QK-table lookups +
//                       smem V-table; FF + logits with packed fma.rn.f32x2.
// ---------------------------------------------------------------------------

#define VOCAB   65
#define NEMB    32
#define TBLK    8
#define NPAIR   36          // causal (t,s) pairs
#define NTV     (TBLK*VOCAB)        // 520

__device__ float g_QT[NTV * NEMB];
__device__ float g_KT[NTV * NEMB];
__device__ float g_VT[NTV * NEMB];
__device__ float g_QK[NPAIR * VOCAB * VOCAB * 4];

// ---------------- packed f32x2 helpers --------------------------------------
__device__ __forceinline__ unsigned long long pk2(float a, float b) {
    unsigned long long r;
    asm("mov.b64 %0, {%1, %2};" : "=l"(r)
        : "r"(__float_as_uint(a)), "r"(__float_as_uint(b)));
    return r;
}
__device__ __forceinline__ void upk2(float& a, float& b, unsigned long long p) {
    unsigned int x, y;
    asm("mov.b64 {%0, %1}, %2;" : "=r"(x), "=r"(y) : "l"(p));
    a = __uint_as_float(x); b = __uint_as_float(y);
}
__device__ __forceinline__ unsigned long long fma2(unsigned long long a,
                                                   unsigned long long b,
                                                   unsigned long long c) {
    unsigned long long d;
    asm("fma.rn.f32x2 %0, %1, %2, %3;" : "=l"(d) : "l"(a), "l"(b), "l"(c));
    return d;
}

// ---------------- stage 1: per-(t,vocab) q/k/v tables ------------------------
__global__ void build_qkv(const float* __restrict__ tok_emb,
                          const float* __restrict__ pos_emb,
                          const float* __restrict__ Wq,
                          const float* __restrict__ Wk,
                          const float* __restrict__ Wv) {
    int tv = blockIdx.x;            // 0..519
    int t  = tv / VOCAB;
    int v  = tv - t * VOCAB;
    int f  = threadIdx.x;           // 0..31 -> (h,d)
    int h  = f >> 3, d = f & 7;
    float qa = 0.f, ka = 0.f, va = 0.f;
#pragma unroll
    for (int c = 0; c < NEMB; c++) {
        float x = tok_emb[v * NEMB + c] + pos_emb[t * NEMB + c];
        int wi = (h * NEMB + c) * 8 + d;     // [H, C, hs]
        qa = fmaf(x, Wq[wi], qa);
        ka = fmaf(x, Wk[wi], ka);
        va = fmaf(x, Wv[wi], va);
    }
    g_QT[tv * NEMB + f] = qa;
    g_KT[tv * NEMB + f] = ka;
    g_VT[tv * NEMB + f] = va;
}

// ---------------- stage 2: attention-logit table -----------------------------
__global__ void build_qk() {
    int P = blockIdx.y;             // pair index 0..35
    int a = blockIdx.x;             // tok_t 0..64
    // decode P -> (t, s)
    int t = 0, rem = P;
    while (rem > t) { rem -= (t + 1); t++; }
    int s = rem;
    const float scale = 0.17677669529663687f;   // 32^-0.5  (n_embed!)
    for (int u = threadIdx.x; u < VOCAB * 4; u += blockDim.x) {
        int b = u >> 2, h = u & 3;
        const float* qp = &g_QT[(t * VOCAB + a) * NEMB + h * 8];
        const float* kp = &g_KT[(s * VOCAB + b) * NEMB + h * 8];
        float acc = 0.f;
#pragma unroll
        for (int d = 0; d < 8; d++) acc = fmaf(qp[d], kp[d], acc);
        g_QK[((P * VOCAB + a) * VOCAB + b) * 4 + h] = acc * scale;
    }
}

// ---------------- stage 3: main --------------------------------------------
// smem layout (floats): VT padded rows of 36 (bank de-conflict), Wf, Wl (rows
// padded to 66 for 8B alignment), bf, bl.
#define SVT_OFF  0
#define SWF_OFF  (NTV * 36)                 // 18720
#define SWL_OFF  (SWF_OFF + 1024)           // 19744
#define SBF_OFF  (SWL_OFF + 32 * 66)        // 21856
#define SBL_OFF  (SBF_OFF + 32)             // 21888
#define SMEM_FLOATS (SBL_OFF + 66)          // 21954
#define SMEM_BYTES  (SMEM_FLOATS * 4)       // 87816

__global__ __launch_bounds__(256, 2)
void bigram_main(const int* __restrict__ idx,
                 const float* __restrict__ Wf, const float* __restrict__ bf,
                 const float* __restrict__ Wl, const float* __restrict__ bl,
                 float* __restrict__ out, int nb) {
    extern __shared__ float sm[];
    int tid = threadIdx.x;

    // --- cooperative smem fill ---
    for (int r = tid; r < NTV; r += 256) {
        const float4* src = (const float4*)(g_VT + r * NEMB);
        float4* dst = (float4*)(sm + SVT_OFF + r * 36);   // r*36 % 4 == 0
#pragma unroll
        for (int q = 0; q < 8; q++) dst[q] = src[q];
    }
    for (int i = tid; i < 1024; i += 256) sm[SWF_OFF + i] = Wf[i];
    for (int i = tid; i < 32 * 65; i += 256) {
        int j = i / 65, v = i - j * 65;
        sm[SWL_OFF + j * 66 + v] = Wl[i];
    }
    if (tid < 32) sm[SBF_OFF + tid] = bf[tid];
    if (tid < 65) sm[SBL_OFF + tid] = bl[tid];
    if (tid == 65) sm[SBL_OFF + 65] = 0.f;
    __syncthreads();

    const float4* QK4 = (const float4*)g_QK;

    for (int b = blockIdx.x * 256 + tid; b < nb; b += gridDim.x * 256) {
        const int4* ip = (const int4*)(idx + (size_t)b * 8);
        int4 ia = ip[0], ibv = ip[1];
        int tok[8] = { ia.x, ia.y, ia.z, ia.w, ibv.x, ibv.y, ibv.z, ibv.w };

        float* orow = out + (size_t)b * (TBLK * VOCAB);

#pragma unroll 1
        for (int t = 0; t < TBLK; t++) {
            // ---- attention weights for row t (4 heads packed in float4) ----
            float4 qk[8];
            int base = (t * (t + 1)) >> 1;
            int at = tok[t] * VOCAB;
            for (int s = 0; s <= t; s++)
                qk[s] = QK4[(base + s) * (VOCAB * VOCAB) + at + tok[s]];

            float4 mx = qk[0];
            for (int s = 1; s <= t; s++) {
                mx.x = fmaxf(mx.x, qk[s].x); mx.y = fmaxf(mx.y, qk[s].y);
                mx.z = fmaxf(mx.z, qk[s].z); mx.w = fmaxf(mx.w, qk[s].w);
            }
            float4 den = make_float4(0.f, 0.f, 0.f, 0.f);
            for (int s = 0; s <= t; s++) {
                qk[s].x = __expf(qk[s].x - mx.x); den.x += qk[s].x;
                qk[s].y = __expf(qk[s].y - mx.y); den.y += qk[s].y;
                qk[s].z = __expf(qk[s].z - mx.z); den.z += qk[s].z;
                qk[s].w = __expf(qk[s].w - mx.w); den.w += qk[s].w;
            }
            float4 inv;
            inv.x = __fdividef(1.f, den.x); inv.y = __fdividef(1.f, den.y);
            inv.z = __fdividef(1.f, den.z); inv.w = __fdividef(1.f, den.w);
            for (int s = 0; s <= t; s++) {
                qk[s].x *= inv.x; qk[s].y *= inv.y;
                qk[s].z *= inv.z; qk[s].w *= inv.w;
            }

            // ---- o[32] = sum_s w[s] * V[s][tok_s][:]  (packed pairs) ----
            unsigned long long o2[16];
#pragma unroll
            for (int g = 0; g < 16; g++) o2[g] = 0ULL;
            for (int s = 0; s <= t; s++) {
                const unsigned long long* V2 = (const unsigned long long*)
                    (sm + SVT_OFF + (s * VOCAB + tok[s]) * 36);
                unsigned long long w0 = pk2(qk[s].x, qk[s].x);
                unsigned long long w1 = pk2(qk[s].y, qk[s].y);
                unsigned long long w2 = pk2(qk[s].z, qk[s].z);
                unsigned long long w3 = pk2(qk[s].w, qk[s].w);
#pragma unroll
                for (int g = 0; g < 4; g++)  o2[g]      = fma2(w0, V2[g],      o2[g]);
#pragma unroll
                for (int g = 0; g < 4; g++)  o2[g + 4]  = fma2(w1, V2[g + 4],  o2[g + 4]);
#pragma unroll
                for (int g = 0; g < 4; g++)  o2[g + 8]  = fma2(w2, V2[g + 8],  o2[g + 8]);
#pragma unroll
                for (int g = 0; g < 4; g++)  o2[g + 12] = fma2(w3, V2[g + 12], o2[g + 12]);
            }
            float o[32];
#pragma unroll
            for (int g = 0; g < 16; g++) upk2(o[2 * g], o[2 * g + 1], o2[g]);

            // ---- FF: y = relu(o @ Wf + bf), packed over j-pairs ----
            unsigned long long y2[16];
            const unsigned long long* bf2 = (const unsigned long long*)(sm + SBF_OFF);
#pragma unroll
            for (int j = 0; j < 16; j++) y2[j] = bf2[j];
#pragma unroll 1
            for (int i = 0; i < 32; i++) {
                unsigned long long a2 = pk2(o[i], o[i]);
                const unsigned long long* w2 =
                    (const unsigned long long*)(sm + SWF_OFF + i * 32);
#pragma unroll
                for (int j = 0; j < 16; j++) y2[j] = fma2(a2, w2[j], y2[j]);
            }
            float y[32];
#pragma unroll
            for (int j = 0; j < 16; j++) {
                float u, v; upk2(u, v, y2[j]);
                y[2 * j]     = fmaxf(u, 0.f);
                y[2 * j + 1] = fmaxf(v, 0.f);
            }

            // ---- logits: z = y @ Wl + bl  (two halves of 32 + v=64) ----
            float* zrow = orow + t * VOCAB;
            {   // v = 0..31
                unsigned long long z2[16];
                const unsigned long long* bl2 = (const unsigned long long*)(sm + SBL_OFF);
#pragma unroll
                for (int v = 0; v < 16; v++) z2[v] = bl2[v];
#pragma unroll 1
                for (int j = 0; j < 32; j++) {
                    unsigned long long p2 = pk2(y[j], y[j]);
                    const unsigned long long* wl2 =
                        (const unsigned long long*)(sm + SWL_OFF + j * 66);
#pragma unroll
                    for (int v = 0; v < 16; v++) z2[v] = fma2(p2, wl2[v], z2[v]);
                }
#pragma unroll
                for (int v = 0; v < 16; v++) {
                    float u, w; upk2(u, w, z2[v]);
                    zrow[2 * v] = u; zrow[2 * v + 1] = w;
                }
            }
            {   // v = 32..63, plus v = 64
                unsigned long long z2[16];
                const unsigned long long* bl2 = (const unsigned long long*)(sm + SBL_OFF);
#pragma unroll
                for (int v = 0; v < 16; v++) z2[v] = bl2[16 + v];
                float z64 = sm[SBL_OFF + 64];
#pragma unroll 1
                for (int j = 0; j < 32; j++) {
                    unsigned long long p2 = pk2(y[j], y[j]);
                    const unsigned long long* wl2 =
                        (const unsigned long long*)(sm + SWL_OFF + j * 66);
#pragma unroll
                    for (int v = 0; v < 16; v++) z2[v] = fma2(p2, wl2[16 + v], z2[v]);
                    z64 = fmaf(y[j], sm[SWL_OFF + j * 66 + 64], z64);
                }
#pragma unroll
                for (int v = 0; v < 16; v++) {
                    float u, w; upk2(u, w, z2[v]);
                    zrow[32 + 2 * v] = u; zrow[33 + 2 * v] = w;
                }
                zrow[64] = z64;
            }
        }
    }
}

// ---------------------------------------------------------------------------
extern "C" void kernel_launch(void* const* d_in, const int* in_sizes, int n_in,
                              void* d_out, int out_size) {
    const int*   idx     = (const int*)  d_in[0];
    const float* tok_emb = (const float*)d_in[1];
    const float* pos_emb = (const float*)d_in[2];
    const float* Wq      = (const float*)d_in[3];
    const float* Wk      = (const float*)d_in[4];
    const float* Wv      = (const float*)d_in[5];
    const float* Wf      = (const float*)d_in[6];
    const float* bf      = (const float*)d_in[7];
    const float* Wl      = (const float*)d_in[8];
    const float* bl      = (const float*)d_in[9];
    float* out = (float*)d_out;

    int nb = in_sizes[0] / TBLK;   // 131072

    cudaFuncSetAttribute(bigram_main,
                         cudaFuncAttributeMaxDynamicSharedMemorySize, SMEM_BYTES);

    build_qkv<<<NTV, 32>>>(tok_emb, pos_emb, Wq, Wk, Wv);
    build_qk<<<dim3(VOCAB, NPAIR), 256>>>();

    int grid = 296;   // 148 SMs x 2 resident blocks -> single wave, grid-stride
    bigram_main<<<grid, 256, SMEM_BYTES>>>(idx, Wf, bf, Wl, bl, out, nb);
}

// round 2
// speedup vs baseline: 2.1549x; 2.1549x over previous
#include <cuda_runtime.h>
#include <cstdint>

// ---------------------------------------------------------------------------
// BigramLM forward, GB300 sm_103a.
//   build_qkv: QT/KT/VT[t][v][f] tables (520 x 32 each)
//   build_qk : QK[pair(t,s)][tok_t][tok_s][h] = q.k * 32^-0.5   (2.43MB, L2)
//   build_vf : VF[t][v][:] = VT[t][v] @ Wf + bf    (FF folded; softmax sums to 1)
//   main     : one batch/thread, t-pair blocking, packed fma.rn.f32x2,
//              smem-staged coalesced streaming stores.
// ---------------------------------------------------------------------------

#define VOCAB   65
#define NEMB    32
#define TBLK    8
#define NPAIR   36
#define NTV     (TBLK*VOCAB)        // 520

typedef unsigned long long u64;

__device__ float g_QT[NTV * NEMB];
__device__ float g_KT[NTV * NEMB];
__device__ float g_VT[NTV * NEMB];
__device__ float g_VF[NTV * NEMB];
__device__ float g_QK[NPAIR * VOCAB * VOCAB * 4];

// ---------------- packed f32x2 helpers --------------------------------------
__device__ __forceinline__ u64 pk2(float a, float b) {
    u64 r;
    asm("mov.b64 %0, {%1, %2};" : "=l"(r)
        : "r"(__float_as_uint(a)), "r"(__float_as_uint(b)));
    return r;
}
__device__ __forceinline__ void upk2(float& a, float& b, u64 p) {
    unsigned int x, y;
    asm("mov.b64 {%0, %1}, %2;" : "=r"(x), "=r"(y) : "l"(p));
    a = __uint_as_float(x); b = __uint_as_float(y);
}
__device__ __forceinline__ u64 fma2(u64 a, u64 b, u64 c) {
    u64 d;
    asm("fma.rn.f32x2 %0, %1, %2, %3;" : "=l"(d) : "l"(a), "l"(b), "l"(c));
    return d;
}

// ---------------- stage 1: per-(t,vocab) q/k/v tables ------------------------
__global__ void build_qkv(const float* __restrict__ tok_emb,
                          const float* __restrict__ pos_emb,
                          const float* __restrict__ Wq,
                          const float* __restrict__ Wk,
                          const float* __restrict__ Wv) {
    int tv = blockIdx.x;            // 0..519
    int t  = tv / VOCAB;
    int v  = tv - t * VOCAB;
    int f  = threadIdx.x;           // 0..31 -> (h,d)
    int h  = f >> 3, d = f & 7;
    float qa = 0.f, ka = 0.f, va = 0.f;
#pragma unroll
    for (int c = 0; c < NEMB; c++) {
        float x = tok_emb[v * NEMB + c] + pos_emb[t * NEMB + c];
        int wi = (h * NEMB + c) * 8 + d;     // [H, C, hs]
        qa = fmaf(x, Wq[wi], qa);
        ka = fmaf(x, Wk[wi], ka);
        va = fmaf(x, Wv[wi], va);
    }
    g_QT[tv * NEMB + f] = qa;
    g_KT[tv * NEMB + f] = ka;
    g_VT[tv * NEMB + f] = va;
}

// ---------------- stage 2a: attention-logit table ----------------------------
__global__ void build_qk() {
    int P = blockIdx.y;             // pair index 0..35
    int a = blockIdx.x;             // tok_t 0..64
    int t = 0, rem = P;
    while (rem > t) { rem -= (t + 1); t++; }
    int s = rem;
    const float scale = 0.17677669529663687f;   // 32^-0.5 (n_embed!)
    for (int u = threadIdx.x; u < VOCAB * 4; u += blockDim.x) {
        int b = u >> 2, h = u & 3;
        const float* qp = &g_QT[(t * VOCAB + a) * NEMB + h * 8];
        const float* kp = &g_KT[(s * VOCAB + b) * NEMB + h * 8];
        float acc = 0.f;
#pragma unroll
        for (int d = 0; d < 8; d++) acc = fmaf(qp[d], kp[d], acc);
        g_QK[((P * VOCAB + a) * VOCAB + b) * 4 + h] = acc * scale;
    }
}

// ---------------- stage 2b: fold FF into V table ------------------------------
__global__ void build_vf(const float* __restrict__ Wf,
                         const float* __restrict__ bf) {
    int tv = blockIdx.x;            // 0..519
    int j  = threadIdx.x;           // 0..31
    const float* vr = g_VT + tv * NEMB;
    float acc = bf[j];
#pragma unroll
    for (int c = 0; c < NEMB; c++)
        acc = fmaf(vr[c], Wf[c * NEMB + j], acc);
    g_VF[tv * NEMB + j] = acc;
}

// ---------------- stage 3: main ----------------------------------------------
// smem float offsets
#define SVF  0                      // VF rows padded to 34 floats
#define SWL  (NTV * 34)             // 17680 ; Wl rows padded to 66
#define SBL  (SWL + 32 * 66)        // 19792 ; bl (66, padded)
#define STG  (SBL + 66)             // 19858 ; staging [256][130]
#define SMEM_FLOATS (STG + 256 * 130)
#define SMEM_BYTES  (SMEM_FLOATS * 4)   // 212,552 bytes

template<int TA>
__device__ __forceinline__ void process_pair(const float4* __restrict__ QK4,
                                             const float* __restrict__ sm,
                                             const int* tok,
                                             float* __restrict__ srow) {
    constexpr int TB = TA + 1;
    // ---- gather QK + exp (values are tiny: no max-subtraction needed) ----
    float4 ea[TA + 1], eb[TB + 1];
    float4 sa = make_float4(0.f, 0.f, 0.f, 0.f);
    float4 sb = make_float4(0.f, 0.f, 0.f, 0.f);
    const int base_a = TA * (TA + 1) / 2;
    const int base_b = base_a + TA + 1;
    const int ra = tok[TA] * VOCAB;
    const int rb = tok[TB] * VOCAB;
#pragma unroll
    for (int s = 0; s <= TA; s++) {
        float4 q = QK4[(base_a + s) * (VOCAB * VOCAB) + ra + tok[s]];
        q.x = __expf(q.x); q.y = __expf(q.y); q.z = __expf(q.z); q.w = __expf(q.w);
        ea[s] = q;
        sa.x += q.x; sa.y += q.y; sa.z += q.z; sa.w += q.w;
    }
#pragma unroll
    for (int s = 0; s <= TB; s++) {
        float4 q = QK4[(base_b + s) * (VOCAB * VOCAB) + rb + tok[s]];
        q.x = __expf(q.x); q.y = __expf(q.y); q.z = __expf(q.z); q.w = __expf(q.w);
        eb[s] = q;
        sb.x += q.x; sb.y += q.y; sb.z += q.z; sb.w += q.w;
    }
    float4 ia4, ib4;
    ia4.x = __fdividef(1.f, sa.x); ia4.y = __fdividef(1.f, sa.y);
    ia4.z = __fdividef(1.f, sa.z); ia4.w = __fdividef(1.f, sa.w);
    ib4.x = __fdividef(1.f, sb.x); ib4.y = __fdividef(1.f, sb.y);
    ib4.z = __fdividef(1.f, sb.z); ib4.w = __fdividef(1.f, sb.w);

    // ---- h = sum_s w_s * VF[s,tok_s]  (FF + bias folded into VF) ----
    u64 ha[16], hb[16];
#pragma unroll
    for (int g = 0; g < 16; g++) { ha[g] = 0ULL; hb[g] = 0ULL; }
#pragma unroll
    for (int s = 0; s <= TA; s++) {
        const u64* v2 = (const u64*)(sm + SVF + (s * VOCAB + tok[s]) * 34);
        u64 wa2[4], wb2[4];
        wa2[0] = pk2(ea[s].x * ia4.x, ea[s].x * ia4.x);
        wa2[1] = pk2(ea[s].y * ia4.y, ea[s].y * ia4.y);
        wa2[2] = pk2(ea[s].z * ia4.z, ea[s].z * ia4.z);
        wa2[3] = pk2(ea[s].w * ia4.w, ea[s].w * ia4.w);
        wb2[0] = pk2(eb[s].x * ib4.x, eb[s].x * ib4.x);
        wb2[1] = pk2(eb[s].y * ib4.y, eb[s].y * ib4.y);
        wb2[2] = pk2(eb[s].z * ib4.z, eb[s].z * ib4.z);
        wb2[3] = pk2(eb[s].w * ib4.w, eb[s].w * ib4.w);
#pragma unroll
        for (int g = 0; g < 16; g++) {
            u64 r = v2[g];
            ha[g] = fma2(wa2[g >> 2], r, ha[g]);
            hb[g] = fma2(wb2[g >> 2], r, hb[g]);
        }
    }
    {   // extra s = TB row for b only
        const u64* v2 = (const u64*)(sm + SVF + (TB * VOCAB + tok[TB]) * 34);
        u64 wb2[4];
        wb2[0] = pk2(eb[TB].x * ib4.x, eb[TB].x * ib4.x);
        wb2[1] = pk2(eb[TB].y * ib4.y, eb[TB].y * ib4.y);
        wb2[2] = pk2(eb[TB].z * ib4.z, eb[TB].z * ib4.z);
        wb2[3] = pk2(eb[TB].w * ib4.w, eb[TB].w * ib4.w);
#pragma unroll
        for (int g = 0; g < 16; g++)
            hb[g] = fma2(wb2[g >> 2], v2[g], hb[g]);
    }

    // ---- relu ----
    float ya[32], yb[32];
#pragma unroll
    for (int g = 0; g < 16; g++) {
        float u, v;
        upk2(u, v, ha[g]);
        ya[2 * g] = fmaxf(u, 0.f); ya[2 * g + 1] = fmaxf(v, 0.f);
        upk2(u, v, hb[g]);
        yb[2 * g] = fmaxf(u, 0.f); yb[2 * g + 1] = fmaxf(v, 0.f);
    }

    // ---- logits for both rows, v in two halves of 32 (+ v=64) ----
    const u64* bl2 = (const u64*)(sm + SBL);
#pragma unroll
    for (int h2 = 0; h2 < 2; h2++) {
        u64 za[16], zb[16];
#pragma unroll
        for (int v = 0; v < 16; v++) { za[v] = bl2[h2 * 16 + v]; zb[v] = za[v]; }
        float z64a = sm[SBL + 64], z64b = z64a;
#pragma unroll 4
        for (int j = 0; j < 32; j++) {
            u64 pa = pk2(ya[j], ya[j]);
            u64 pb = pk2(yb[j], yb[j]);
            const u64* w2 = (const u64*)(sm + SWL + j * 66) + h2 * 16;
#pragma unroll
            for (int v = 0; v < 16; v++) {
                u64 w = w2[v];
                za[v] = fma2(pa, w, za[v]);
                zb[v] = fma2(pb, w, zb[v]);
            }
            if (h2 == 1) {
                float wl = sm[SWL + j * 66 + 64];
                z64a = fmaf(ya[j], wl, z64a);
                z64b = fmaf(yb[j], wl, z64b);
            }
        }
        // stage: row layout = [a: floats 0..64][b: floats 65..129]
        u64* sa64 = (u64*)srow;
#pragma unroll
        for (int v = 0; v < 16; v++) sa64[h2 * 16 + v] = za[v];
#pragma unroll
        for (int v = 0; v < 16; v++) {
            float u, w; upk2(u, w, zb[v]);
            srow[65 + h2 * 32 + 2 * v]     = u;
            srow[65 + h2 * 32 + 2 * v + 1] = w;
        }
        if (h2 == 1) { srow[64] = z64a; srow[129] = z64b; }
    }
}

__global__ __launch_bounds__(256, 1)
void bigram_main(const int* __restrict__ idx,
                 const float* __restrict__ Wl, const float* __restrict__ bl,
                 float* __restrict__ out, int nb) {
    extern __shared__ float sm[];
    int tid = threadIdx.x;

    // --- cooperative smem fill ---
    for (int r = tid; r < NTV; r += 256) {
        const u64* src = (const u64*)(g_VF + r * NEMB);
        u64* dst = (u64*)(sm + SVF + r * 34);
#pragma unroll
        for (int g = 0; g < 16; g++) dst[g] = src[g];
    }
    for (int i = tid; i < 32 * 65; i += 256) {
        int j = i / 65, v = i - j * 65;
        sm[SWL + j * 66 + v] = Wl[i];
    }
    if (tid < 32) sm[SWL + tid * 66 + 65] = 0.f;
    if (tid < 65) sm[SBL + tid] = bl[tid];
    if (tid == 65) sm[SBL + 65] = 0.f;
    __syncthreads();

    const float4* QK4 = (const float4*)g_QK;
    int ntile = (nb + 255) >> 8;

    for (int tile = blockIdx.x; tile < ntile; tile += gridDim.x) {
        int b = tile * 256 + tid;
        int tok[8];
        if (b < nb) {
            const int4* ip = (const int4*)(idx + (size_t)b * 8);
            int4 a = ip[0], c = ip[1];
            tok[0] = a.x; tok[1] = a.y; tok[2] = a.z; tok[3] = a.w;
            tok[4] = c.x; tok[5] = c.y; tok[6] = c.z; tok[7] = c.w;
        }
        float* srow = sm + STG + tid * 130;
        const u64* stg64 = (const u64*)(sm + STG);
        int gbase = tile * 256;

#define DO_PAIR(TA)                                                         \
        {                                                                   \
            if (b < nb) process_pair<TA>(QK4, sm, tok, srow);               \
            __syncthreads();                                                \
            for (int u = tid; u < 256 * 65; u += 256) {                     \
                int b2 = u / 65, e = u - b2 * 65;                           \
                int gb = gbase + b2;                                        \
                if (gb < nb) {                                              \
                    u64 val = stg64[b2 * 65 + e];                           \
                    __stcs((u64*)(out + (size_t)gb * (TBLK * VOCAB)         \
                                      + (TA) * VOCAB) + e, val);            \
                }                                                           \
            }                                                               \
            __syncthreads();                                                \
        }

        DO_PAIR(0)
        DO_PAIR(2)
        DO_PAIR(4)
        DO_PAIR(6)
#undef DO_PAIR
    }
}

// ---------------------------------------------------------------------------
extern "C" void kernel_launch(void* const* d_in, const int* in_sizes, int n_in,
                              void* d_out, int out_size) {
    const int*   idx     = (const int*)  d_in[0];
    const float* tok_emb = (const float*)d_in[1];
    const float* pos_emb = (const float*)d_in[2];
    const float* Wq      = (const float*)d_in[3];
    const float* Wk      = (const float*)d_in[4];
    const float* Wv      = (const float*)d_in[5];
    const float* Wf      = (const float*)d_in[6];
    const float* bf      = (const float*)d_in[7];
    const float* Wl      = (const float*)d_in[8];
    const float* bl      = (const float*)d_in[9];
    float* out = (float*)d_out;

    int nb = in_sizes[0] / TBLK;   // 131072

    cudaFuncSetAttribute(bigram_main,
                         cudaFuncAttributeMaxDynamicSharedMemorySize, SMEM_BYTES);

    int dev = 0, nsm = 148;
    cudaGetDevice(&dev);
    cudaDeviceGetAttribute(&nsm, cudaDevAttrMultiProcessorCount, dev);

    build_qkv<<<NTV, 32>>>(tok_emb, pos_emb, Wq, Wk, Wv);
    build_qk<<<dim3(VOCAB, NPAIR), 256>>>();
    build_vf<<<NTV, 32>>>(Wf, bf);

    bigram_main<<<nsm, 256, SMEM_BYTES>>>(idx, Wl, bl, out, nb);
}